// round 1
// baseline (speedup 1.0000x reference)
#include <cuda_runtime.h>
#include <cstdint>

// GCN 2-layer: out = log_softmax( A_norm * relu(A_norm * (x@W1) + b1) @ W2 + b2 )
// A_norm includes self loops; norm[e] = dinv[src]*dinv[dst], dinv = rsqrt(deg_dst).

#define MAXN 100000

__device__ __align__(16) float g_dinv[MAXN];          // deg -> dinv in place
__device__ __align__(16) float g_h  [MAXN * 128];     // x@W1, then relu(agg+b1)
__device__ __align__(16) float g_agg[MAXN * 128];     // layer-1 aggregation
__device__ __align__(16) float g_h2 [MAXN * 64];      // h1@W2
__device__ int g_is32;                                 // 1 if edge_index is int32

__device__ __forceinline__ int edge_at(const void* ei, long long pos, int is32) {
    if (is32) return ((const int*)ei)[pos];
    return (int)(((const long long*)ei)[pos]);
}

// ---------------------------------------------------------------- init / dtype detect
__global__ void k_init(int n) {
    int i = blockIdx.x * blockDim.x + threadIdx.x;
    if (i < n) g_dinv[i] = 1.0f;          // self-loop contributes 1 to every degree
    if (i == 0) g_is32 = 0;
}

// If edge_index is int64 (values < 2^31, nonneg), every odd 32-bit word is 0.
// If int32, odd words are random node indices -> some nonzero with certainty.
__global__ void k_detect(const unsigned int* e, int nwords) {
    int i = blockIdx.x * blockDim.x + threadIdx.x;
    int idx = 2 * i + 1;
    if (idx < nwords && e[idx] != 0u) atomicOr(&g_is32, 1);
}

// ---------------------------------------------------------------- degree / dinv
__global__ void k_deg(const void* ei, int E) {
    int i = blockIdx.x * blockDim.x + threadIdx.x;
    if (i >= E) return;
    int is32 = g_is32;
    int d = edge_at(ei, (long long)E + i, is32);
    atomicAdd(&g_dinv[d], 1.0f);
}

__global__ void k_rsqrt(int n) {
    int i = blockIdx.x * blockDim.x + threadIdx.x;
    if (i < n) g_dinv[i] = rsqrtf(g_dinv[i]);
}

// ---------------------------------------------------------------- GEMM1: h = x @ W1  [N,128]x[128,128]
// 64 rows/block, 256 threads, each thread: 8 rows x 4 cols register tile.
__global__ void k_gemm1(const float* __restrict__ x, const float* __restrict__ W, int N) {
    __shared__ float xs[64][132];   // +4 pad (row stride 528B, 16B aligned)
    int row0 = blockIdx.x * 64;
    int tid  = threadIdx.x;
    const float4* x4 = (const float4*)x;

    for (int i = tid; i < 64 * 32; i += 256) {
        int r = i >> 5, c4 = i & 31;
        int gr = row0 + r;
        float4 v = make_float4(0.f, 0.f, 0.f, 0.f);
        if (gr < N) v = x4[(size_t)gr * 32 + c4];
        *(float4*)&xs[r][c4 * 4] = v;
    }
    __syncthreads();

    int tx = tid & 31;   // column group: cols tx*4..tx*4+3
    int ty = tid >> 5;   // row group: rows ty*8..ty*8+7
    float acc[8][4];
#pragma unroll
    for (int r = 0; r < 8; r++)
#pragma unroll
        for (int c = 0; c < 4; c++) acc[r][c] = 0.f;

    const float4* W4 = (const float4*)W;
#pragma unroll 4
    for (int k = 0; k < 128; k++) {
        float4 w = __ldg(&W4[k * 32 + tx]);
#pragma unroll
        for (int r = 0; r < 8; r++) {
            float xv = xs[ty * 8 + r][k];
            acc[r][0] += xv * w.x;
            acc[r][1] += xv * w.y;
            acc[r][2] += xv * w.z;
            acc[r][3] += xv * w.w;
        }
    }

    float4* h4 = (float4*)g_h;
#pragma unroll
    for (int r = 0; r < 8; r++) {
        int gr = row0 + ty * 8 + r;
        if (gr < N)
            h4[(size_t)gr * 32 + tx] = make_float4(acc[r][0], acc[r][1], acc[r][2], acc[r][3]);
    }
}

// ---------------------------------------------------------------- self-loop init: agg[i] = h[i]*dinv[i]^2
__global__ void k_selfinit1(int N) {
    int i = blockIdx.x * blockDim.x + threadIdx.x;      // over N*32 float4s
    if (i >= N * 32) return;
    int row = i >> 5;
    float w = g_dinv[row]; w *= w;
    float4 v = ((const float4*)g_h)[i];
    v.x *= w; v.y *= w; v.z *= w; v.w *= w;
    ((float4*)g_agg)[i] = v;
}

// ---------------------------------------------------------------- edge scatter layer 1 (128 dims, warp/edge)
__global__ void k_scatter1(const void* ei, int E) {
    int lane  = threadIdx.x & 31;
    int warp  = (blockIdx.x * blockDim.x + threadIdx.x) >> 5;
    int nwarp = (gridDim.x * blockDim.x) >> 5;
    int is32  = g_is32;
    const float4* h4 = (const float4*)g_h;
    for (int e = warp; e < E; e += nwarp) {
        int s = edge_at(ei, e, is32);
        int d = edge_at(ei, (long long)E + e, is32);
        float w = g_dinv[s] * g_dinv[d];
        float4 v = h4[(size_t)s * 32 + lane];
        v.x *= w; v.y *= w; v.z *= w; v.w *= w;
        float* p = g_agg + (size_t)d * 128 + lane * 4;
        asm volatile("red.global.add.v4.f32 [%0], {%1,%2,%3,%4};"
                     :: "l"(p), "f"(v.x), "f"(v.y), "f"(v.z), "f"(v.w) : "memory");
    }
}

// ---------------------------------------------------------------- h1 = relu(agg + b1) -> g_h (reuse)
__global__ void k_relu(const float* __restrict__ b1, int N) {
    int i = blockIdx.x * blockDim.x + threadIdx.x;      // over N*32 float4s
    if (i >= N * 32) return;
    int c4 = i & 31;
    float4 b = ((const float4*)b1)[c4];
    float4 v = ((const float4*)g_agg)[i];
    v.x = fmaxf(v.x + b.x, 0.f);
    v.y = fmaxf(v.y + b.y, 0.f);
    v.z = fmaxf(v.z + b.z, 0.f);
    v.w = fmaxf(v.w + b.w, 0.f);
    ((float4*)g_h)[i] = v;
}

// ---------------------------------------------------------------- GEMM2: h2 = h1 @ W2  [N,128]x[128,64]
// 64 rows/block, 256 threads, each thread: 4 rows x 4 cols.
__global__ void k_gemm2(const float* __restrict__ W, int N) {
    __shared__ float xs[64][132];
    int row0 = blockIdx.x * 64;
    int tid  = threadIdx.x;
    const float4* x4 = (const float4*)g_h;

    for (int i = tid; i < 64 * 32; i += 256) {
        int r = i >> 5, c4 = i & 31;
        int gr = row0 + r;
        float4 v = make_float4(0.f, 0.f, 0.f, 0.f);
        if (gr < N) v = x4[(size_t)gr * 32 + c4];
        *(float4*)&xs[r][c4 * 4] = v;
    }
    __syncthreads();

    int tx = tid & 15;   // cols tx*4..tx*4+3 (64 cols)
    int ty = tid >> 4;   // rows ty*4..ty*4+3 (16 groups * 4 = 64 rows)
    float acc[4][4];
#pragma unroll
    for (int r = 0; r < 4; r++)
#pragma unroll
        for (int c = 0; c < 4; c++) acc[r][c] = 0.f;

    const float4* W4 = (const float4*)W;
#pragma unroll 4
    for (int k = 0; k < 128; k++) {
        float4 w = __ldg(&W4[k * 16 + tx]);
#pragma unroll
        for (int r = 0; r < 4; r++) {
            float xv = xs[ty * 4 + r][k];
            acc[r][0] += xv * w.x;
            acc[r][1] += xv * w.y;
            acc[r][2] += xv * w.z;
            acc[r][3] += xv * w.w;
        }
    }

    float4* o4 = (float4*)g_h2;
#pragma unroll
    for (int r = 0; r < 4; r++) {
        int gr = row0 + ty * 4 + r;
        if (gr < N)
            o4[(size_t)gr * 16 + tx] = make_float4(acc[r][0], acc[r][1], acc[r][2], acc[r][3]);
    }
}

// ---------------------------------------------------------------- self-loop init layer 2 -> d_out
__global__ void k_selfinit2(float* __restrict__ out, int N) {
    int i = blockIdx.x * blockDim.x + threadIdx.x;      // over N*16 float4s
    if (i >= N * 16) return;
    int row = i >> 4;
    float w = g_dinv[row]; w *= w;
    float4 v = ((const float4*)g_h2)[i];
    v.x *= w; v.y *= w; v.z *= w; v.w *= w;
    ((float4*)out)[i] = v;
}

// ---------------------------------------------------------------- edge scatter layer 2 (64 dims, warp/edge, v2 red)
__global__ void k_scatter2(const void* ei, float* __restrict__ out, int E) {
    int lane  = threadIdx.x & 31;
    int warp  = (blockIdx.x * blockDim.x + threadIdx.x) >> 5;
    int nwarp = (gridDim.x * blockDim.x) >> 5;
    int is32  = g_is32;
    const float2* h2 = (const float2*)g_h2;
    for (int e = warp; e < E; e += nwarp) {
        int s = edge_at(ei, e, is32);
        int d = edge_at(ei, (long long)E + e, is32);
        float w = g_dinv[s] * g_dinv[d];
        float2 v = h2[(size_t)s * 32 + lane];
        v.x *= w; v.y *= w;
        float* p = out + (size_t)d * 64 + lane * 2;
        asm volatile("red.global.add.v2.f32 [%0], {%1,%2};"
                     :: "l"(p), "f"(v.x), "f"(v.y) : "memory");
    }
}

// ---------------------------------------------------------------- log_softmax over 64 cols (warp/row), += b2
__global__ void k_lsm(float* __restrict__ out, const float* __restrict__ b2, int N) {
    int lane = threadIdx.x & 31;
    int row  = (blockIdx.x * blockDim.x + threadIdx.x) >> 5;
    if (row >= N) return;
    float* r = out + (size_t)row * 64;
    float v0 = r[lane]      + b2[lane];
    float v1 = r[lane + 32] + b2[lane + 32];
    float m = fmaxf(v0, v1);
#pragma unroll
    for (int o = 16; o; o >>= 1) m = fmaxf(m, __shfl_xor_sync(0xFFFFFFFFu, m, o));
    float s = __expf(v0 - m) + __expf(v1 - m);
#pragma unroll
    for (int o = 16; o; o >>= 1) s += __shfl_xor_sync(0xFFFFFFFFu, s, o);
    float lg = m + logf(s);
    r[lane]      = v0 - lg;
    r[lane + 32] = v1 - lg;
}

// ================================================================ launch
extern "C" void kernel_launch(void* const* d_in, const int* in_sizes, int n_in,
                              void* d_out, int out_size) {
    const float* x  = (const float*)d_in[0];
    const void*  ei = d_in[1];
    const float* W1 = (const float*)d_in[2];
    const float* b1 = (const float*)d_in[3];
    const float* W2 = (const float*)d_in[4];
    const float* b2 = (const float*)d_in[5];
    float* out = (float*)d_out;

    int N = in_sizes[0] / 128;       // 100000
    int E = in_sizes[1] / 2;         // 1600000

    k_init<<<(N + 255) / 256, 256>>>(N);
    k_detect<<<128, 256>>>((const unsigned int*)ei, 2 * E);
    k_deg<<<(E + 255) / 256, 256>>>(ei, E);
    k_rsqrt<<<(N + 255) / 256, 256>>>(N);

    k_gemm1<<<(N + 63) / 64, 256>>>(x, W1, N);
    k_selfinit1<<<(N * 32 + 255) / 256, 256>>>(N);
    k_scatter1<<<2048, 256>>>(ei, E);
    k_relu<<<(N * 32 + 255) / 256, 256>>>(b1, N);

    k_gemm2<<<(N + 63) / 64, 256>>>(W2, N);
    k_selfinit2<<<(N * 16 + 255) / 256, 256>>>(out, N);
    k_scatter2<<<2048, 256>>>(ei, out, E);
    k_lsm<<<(N * 32 + 255) / 256, 256>>>(out, b2, N);
}

// round 2
// speedup vs baseline: 1.5226x; 1.5226x over previous
#include <cuda_runtime.h>
#include <cstdint>

// GCN 2-layer: out = log_softmax( A * relu(A * (x@W1) + b1) @ W2 + b2 )
// A includes self loops; norm[e] = dinv[src]*dinv[dst], dinv = rsqrt(deg_dst).
// Strategy: build dst-sorted CSR once, then warp-per-node GATHER (no atomics
// in the feature aggregation), with bias/relu/log_softmax fused in epilogues.

#define MAXN 100000
#define MAXE 1600000

__device__ __align__(16) float g_dinv[MAXN];
__device__ int   g_cnt [MAXN];           // in-degree (excl self loop)
__device__ int   g_row [MAXN];           // CSR row start (exclusive scan of cnt)
__device__ int   g_cur [MAXN];           // fill cursors
__device__ int   g_bsum[128];            // block partial sums for scan
__device__ __align__(16) int   g_ssrc[MAXE];   // src ids, sorted by dst
__device__ __align__(16) float g_sw  [MAXE];   // norm weight per sorted edge
__device__ __align__(16) float g_h  [MAXN * 128];   // x@W1
__device__ __align__(16) float g_hb [MAXN * 128];   // relu(A*h + b1)
__device__ __align__(16) float g_h2 [MAXN * 64];    // hb@W2
__device__ int g_is32;

__device__ __forceinline__ int edge_at(const void* ei, long long pos, int is32) {
    if (is32) return ((const int*)ei)[pos];
    return (int)(((const long long*)ei)[pos]);
}

// ------------------------------------------------------------ init / dtype detect
__global__ void k_init(int n) {
    int i = blockIdx.x * blockDim.x + threadIdx.x;
    if (i < n) g_cnt[i] = 0;
    if (i == 0) g_is32 = 0;
}

__global__ void k_detect(const unsigned int* e, int nwords) {
    int i = blockIdx.x * blockDim.x + threadIdx.x;
    int idx = 2 * i + 1;
    if (idx < nwords && e[idx] != 0u) atomicOr(&g_is32, 1);
}

// ------------------------------------------------------------ degree histogram
__global__ void k_deg(const void* ei, int E) {
    int i = blockIdx.x * blockDim.x + threadIdx.x;
    if (i >= E) return;
    int d = edge_at(ei, (long long)E + i, g_is32);
    atomicAdd(&g_cnt[d], 1);
}

// ------------------------------------------------------------ prefix scan (3 stages)
__global__ void k_scan1(int n) {      // per-block exclusive scan of g_cnt
    __shared__ int sm[1024];
    int tid = threadIdx.x;
    int i = blockIdx.x * 1024 + tid;
    int v = (i < n) ? g_cnt[i] : 0;
    sm[tid] = v;
    __syncthreads();
#pragma unroll
    for (int o = 1; o < 1024; o <<= 1) {
        int t = (tid >= o) ? sm[tid - o] : 0;
        __syncthreads();
        sm[tid] += t;
        __syncthreads();
    }
    if (i < n) g_row[i] = sm[tid] - v;          // exclusive within block
    if (tid == 1023) g_bsum[blockIdx.x] = sm[tid];
}

__global__ void k_scan2(int nb) {     // scan the 98 block sums (tiny, serial)
    if (threadIdx.x == 0) {
        int acc = 0;
        for (int b = 0; b < nb; b++) { int t = g_bsum[b]; g_bsum[b] = acc; acc += t; }
    }
}

__global__ void k_scan3(int n) {      // add block offsets, reset cursors, dinv
    int i = blockIdx.x * blockDim.x + threadIdx.x;
    if (i >= n) return;
    g_row[i] += g_bsum[i >> 10];
    g_cur[i] = 0;
    g_dinv[i] = rsqrtf(1.0f + (float)g_cnt[i]);   // +1 = self loop
}

// ------------------------------------------------------------ CSR fill
__global__ void k_fill(const void* ei, int E) {
    int e = blockIdx.x * blockDim.x + threadIdx.x;
    if (e >= E) return;
    int is32 = g_is32;
    int s = edge_at(ei, e, is32);
    int d = edge_at(ei, (long long)E + e, is32);
    int pos = g_row[d] + atomicAdd(&g_cur[d], 1);
    g_ssrc[pos] = s;
    g_sw[pos] = g_dinv[s] * g_dinv[d];
}

// ------------------------------------------------------------ GEMM1: h = x @ W1  [N,128]x[128,128]
__global__ void k_gemm1(const float* __restrict__ x, const float* __restrict__ W, int N) {
    __shared__ float xs[64][132];
    int row0 = blockIdx.x * 64;
    int tid  = threadIdx.x;
    const float4* x4 = (const float4*)x;

    for (int i = tid; i < 64 * 32; i += 256) {
        int r = i >> 5, c4 = i & 31;
        int gr = row0 + r;
        float4 v = make_float4(0.f, 0.f, 0.f, 0.f);
        if (gr < N) v = x4[(size_t)gr * 32 + c4];
        *(float4*)&xs[r][c4 * 4] = v;
    }
    __syncthreads();

    int tx = tid & 31, ty = tid >> 5;
    float acc[8][4];
#pragma unroll
    for (int r = 0; r < 8; r++)
#pragma unroll
        for (int c = 0; c < 4; c++) acc[r][c] = 0.f;

    const float4* W4 = (const float4*)W;
#pragma unroll 4
    for (int k = 0; k < 128; k++) {
        float4 w = __ldg(&W4[k * 32 + tx]);
#pragma unroll
        for (int r = 0; r < 8; r++) {
            float xv = xs[ty * 8 + r][k];
            acc[r][0] += xv * w.x; acc[r][1] += xv * w.y;
            acc[r][2] += xv * w.z; acc[r][3] += xv * w.w;
        }
    }
    float4* h4 = (float4*)g_h;
#pragma unroll
    for (int r = 0; r < 8; r++) {
        int gr = row0 + ty * 8 + r;
        if (gr < N)
            h4[(size_t)gr * 32 + tx] = make_float4(acc[r][0], acc[r][1], acc[r][2], acc[r][3]);
    }
}

// ------------------------------------------------------------ agg layer 1: warp/node gather
// hb[i] = relu( dinv[i]^2*h[i] + sum_e w_e*h[src_e] + b1 )
__global__ void k_agg1(const float* __restrict__ b1, int N) {
    int lane = threadIdx.x & 31;
    int node = (blockIdx.x * blockDim.x + threadIdx.x) >> 5;
    if (node >= N) return;
    const float4* h4 = (const float4*)g_h;

    float di = g_dinv[node];
    float4 acc = h4[(size_t)node * 32 + lane];
    float sw = di * di;
    acc.x *= sw; acc.y *= sw; acc.z *= sw; acc.w *= sw;

    int beg = g_row[node];
    int end = beg + g_cnt[node];
#pragma unroll 2
    for (int j = beg; j < end; j++) {
        int   s = __ldg(&g_ssrc[j]);
        float w = __ldg(&g_sw[j]);
        float4 v = h4[(size_t)s * 32 + lane];
        acc.x += v.x * w; acc.y += v.y * w;
        acc.z += v.z * w; acc.w += v.w * w;
    }
    float4 b = ((const float4*)b1)[lane];
    acc.x = fmaxf(acc.x + b.x, 0.f);
    acc.y = fmaxf(acc.y + b.y, 0.f);
    acc.z = fmaxf(acc.z + b.z, 0.f);
    acc.w = fmaxf(acc.w + b.w, 0.f);
    ((float4*)g_hb)[(size_t)node * 32 + lane] = acc;
}

// ------------------------------------------------------------ GEMM2: h2 = hb @ W2  [N,128]x[128,64]
__global__ void k_gemm2(const float* __restrict__ W, int N) {
    __shared__ float xs[64][132];
    int row0 = blockIdx.x * 64;
    int tid  = threadIdx.x;
    const float4* x4 = (const float4*)g_hb;

    for (int i = tid; i < 64 * 32; i += 256) {
        int r = i >> 5, c4 = i & 31;
        int gr = row0 + r;
        float4 v = make_float4(0.f, 0.f, 0.f, 0.f);
        if (gr < N) v = x4[(size_t)gr * 32 + c4];
        *(float4*)&xs[r][c4 * 4] = v;
    }
    __syncthreads();

    int tx = tid & 15, ty = tid >> 4;
    float acc[4][4];
#pragma unroll
    for (int r = 0; r < 4; r++)
#pragma unroll
        for (int c = 0; c < 4; c++) acc[r][c] = 0.f;

    const float4* W4 = (const float4*)W;
#pragma unroll 4
    for (int k = 0; k < 128; k++) {
        float4 w = __ldg(&W4[k * 16 + tx]);
#pragma unroll
        for (int r = 0; r < 4; r++) {
            float xv = xs[ty * 4 + r][k];
            acc[r][0] += xv * w.x; acc[r][1] += xv * w.y;
            acc[r][2] += xv * w.z; acc[r][3] += xv * w.w;
        }
    }
    float4* o4 = (float4*)g_h2;
#pragma unroll
    for (int r = 0; r < 4; r++) {
        int gr = row0 + ty * 4 + r;
        if (gr < N)
            o4[(size_t)gr * 16 + tx] = make_float4(acc[r][0], acc[r][1], acc[r][2], acc[r][3]);
    }
}

// ------------------------------------------------------------ agg layer 2 + bias + log_softmax fused
// out[i] = log_softmax( dinv^2*h2[i] + sum w_e*h2[src] + b2 )
__global__ void k_agg2(const float* __restrict__ b2, float* __restrict__ out, int N) {
    int lane = threadIdx.x & 31;
    int node = (blockIdx.x * blockDim.x + threadIdx.x) >> 5;
    if (node >= N) return;
    const float2* h2 = (const float2*)g_h2;

    float di = g_dinv[node];
    float2 acc = h2[(size_t)node * 32 + lane];
    float sw = di * di;
    acc.x *= sw; acc.y *= sw;

    int beg = g_row[node];
    int end = beg + g_cnt[node];
#pragma unroll 2
    for (int j = beg; j < end; j++) {
        int   s = __ldg(&g_ssrc[j]);
        float w = __ldg(&g_sw[j]);
        float2 v = h2[(size_t)s * 32 + lane];
        acc.x += v.x * w; acc.y += v.y * w;
    }
    float2 b = ((const float2*)b2)[lane];
    acc.x += b.x; acc.y += b.y;

    float m = fmaxf(acc.x, acc.y);
#pragma unroll
    for (int o = 16; o; o >>= 1) m = fmaxf(m, __shfl_xor_sync(0xFFFFFFFFu, m, o));
    float s = __expf(acc.x - m) + __expf(acc.y - m);
#pragma unroll
    for (int o = 16; o; o >>= 1) s += __shfl_xor_sync(0xFFFFFFFFu, s, o);
    float lg = m + logf(s);
    ((float2*)out)[(size_t)node * 32 + lane] = make_float2(acc.x - lg, acc.y - lg);
}

// ============================================================ launch
extern "C" void kernel_launch(void* const* d_in, const int* in_sizes, int n_in,
                              void* d_out, int out_size) {
    const float* x  = (const float*)d_in[0];
    const void*  ei = d_in[1];
    const float* W1 = (const float*)d_in[2];
    const float* b1 = (const float*)d_in[3];
    const float* W2 = (const float*)d_in[4];
    const float* b2 = (const float*)d_in[5];
    float* out = (float*)d_out;

    int N = in_sizes[0] / 128;       // 100000
    int E = in_sizes[1] / 2;         // 1600000
    int nscanblk = (N + 1023) / 1024;

    k_init  <<<(N + 255) / 256, 256>>>(N);
    k_detect<<<128, 256>>>((const unsigned int*)ei, 2 * E);
    k_deg   <<<(E + 255) / 256, 256>>>(ei, E);
    k_scan1 <<<nscanblk, 1024>>>(N);
    k_scan2 <<<1, 32>>>(nscanblk);
    k_scan3 <<<(N + 255) / 256, 256>>>(N);
    k_fill  <<<(E + 255) / 256, 256>>>(ei, E);

    k_gemm1 <<<(N + 63) / 64, 256>>>(x, W1, N);
    k_agg1  <<<(N + 7) / 8, 256>>>(b1, N);
    k_gemm2 <<<(N + 63) / 64, 256>>>(W2, N);
    k_agg2  <<<(N + 7) / 8, 256>>>(b2, out, N);
}